// round 10
// baseline (speedup 1.0000x reference)
#include <cuda_runtime.h>
#include <cstdint>

#define N_NODES 50000
#define N_PAD   50048           // 391 * 128
#define N_EDGES 640000
#define IN_CH   128
#define HID_CH  256
#define K_TOT   256
#define TILE_M  128
#define TILE_N  128
#define N_TILES 391             // ceil(50000/128)
#define CHUNK_K 32
#define PAD     36              // floats per smem row (16B-aligned, ldmatrix conflict-free)
#define EPB     1637            // edges per scatter block: 391*1637 >= 640000

// Scratch (__device__ globals zero-initialized; pad rows never RED'd).
__device__ float g_agg[N_PAD * IN_CH];
__device__ float g_cnt[N_PAD];
__device__ float g_Bt[HID_CH * K_TOT];   // Bt[n][k] = Wcat[k][n], tf32-rounded

__device__ __forceinline__ uint32_t f2tf(float f) {
    uint32_t r;
    asm("cvt.rna.tf32.f32 %0, %1;" : "=r"(r) : "f"(f));
    return r;
}
__device__ __forceinline__ uint32_t smem_u32(const void* p) {
    return (uint32_t)__cvta_generic_to_shared(p);
}
__device__ __forceinline__ void ldsm_x4(uint32_t& r0, uint32_t& r1,
                                        uint32_t& r2, uint32_t& r3, uint32_t addr) {
    asm volatile("ldmatrix.sync.aligned.m8n8.x4.shared.b16 {%0,%1,%2,%3}, [%4];"
                 : "=r"(r0), "=r"(r1), "=r"(r2), "=r"(r3) : "r"(addr));
}
__device__ __forceinline__ void mma_tf32(float* c, const uint32_t* a,
                                         uint32_t b0, uint32_t b1) {
    asm("mma.sync.aligned.m16n8k8.row.col.f32.tf32.tf32.f32 "
        "{%0,%1,%2,%3}, {%4,%5,%6,%7}, {%8,%9}, {%0,%1,%2,%3};"
        : "+f"(c[0]), "+f"(c[1]), "+f"(c[2]), "+f"(c[3])
        : "r"(a[0]), "r"(a[1]), "r"(a[2]), "r"(a[3]), "r"(b0), "r"(b1));
}

// ---------------------------------------------------------------------------
// Kernel 1: prep — zero accumulators + transpose weights (grid-stride roles).
// ---------------------------------------------------------------------------
__global__ void prep_kernel(const float* __restrict__ W_l,
                            const float* __restrict__ W_r) {
    int idx = blockIdx.x * blockDim.x + threadIdx.x;
    int stride = gridDim.x * blockDim.x;
    const int total4 = (N_PAD * IN_CH) / 4;
    float4 z = make_float4(0.f, 0.f, 0.f, 0.f);
    for (int i = idx; i < total4; i += stride)
        reinterpret_cast<float4*>(g_agg)[i] = z;
    for (int i = idx; i < N_PAD; i += stride) g_cnt[i] = 0.0f;
    for (int i = idx; i < HID_CH * K_TOT; i += stride) {
        int n = i >> 8, k = i & 255;   // K_TOT = 256
        float v = (k < IN_CH) ? W_l[k * HID_CH + n] : W_r[(k - IN_CH) * HID_CH + n];
        g_Bt[n * K_TOT + k] = __uint_as_float(f2tf(v));
    }
}

// ---------------------------------------------------------------------------
// Shared GEMM smem layout (K1 gemm role and K2 both use it).
// ---------------------------------------------------------------------------
#define OFF_BIAS 0
#define OFF_A    512
#define ABYTES   (TILE_M * PAD * 4)        // 18432
#define OFF_B    (OFF_A + 2 * ABYTES)      // 37376
#define SMEM_BYTES (OFF_B + 2 * ABYTES)    // 74240

// ---------------------------------------------------------------------------
// GEMM tile body: C[128x128] = Asrc(K=128) @ g_Bt[:, kofs..kofs+128) (+bias).
// AGG_PATH: A = g_agg*inv(cnt) (padded, unguarded); else A = x (guarded).
// ACCUM_OUT: epilogue does out += acc (no bias); else out = acc + bias.
// ---------------------------------------------------------------------------
template <bool AGG_PATH, bool ACCUM_OUT>
__device__ __forceinline__ void gemm_tile(char* smem, int node0, int nblk0, int kofs,
                                          const float* __restrict__ x,
                                          const float* __restrict__ b_l,
                                          float* __restrict__ out) {
    const int tid = threadIdx.x;
    const int wid = tid >> 5, lid = tid & 31;
    const int lrow = lid >> 2, lane4 = lid & 3;
    const int m_base = (wid & 3) * 32;
    const int n_base = (wid >> 2) * 64;

    float* bias_s = (float*)(smem + OFF_BIAS);
    if (!ACCUM_OUT && tid < TILE_N) bias_s[tid] = b_l[nblk0 + tid];

    const int g = lid >> 3;
    const int rin = lid & 7;
    uint32_t aoff[2];
    #pragma unroll
    for (int mi = 0; mi < 2; ++mi)
        aoff[mi] = ((m_base + mi * 16 + (g & 1) * 8 + rin) * PAD + (g >> 1) * 4) * 4;
    uint32_t boff[4];
    #pragma unroll
    for (int p = 0; p < 4; ++p)
        boff[p] = ((n_base + p * 16 + (g >> 1) * 8 + rin) * PAD + (g & 1) * 4) * 4;

    float4 aregs[4], bregs[4];
    int arow[4];

    auto load_chunk = [&](int c) {
        const int kc = c * CHUNK_K;
        #pragma unroll
        for (int t = 0; t < 4; ++t) {
            int idx = tid + t * 256;
            int row = idx >> 3, j4 = idx & 7;
            int node = node0 + row;
            arow[t] = row * PAD + j4 * 4;
            float4 v;
            if (AGG_PATH) {
                v = *reinterpret_cast<const float4*>(
                        g_agg + (size_t)node * IN_CH + kc + j4 * 4);
                float inv = 1.0f / fmaxf(g_cnt[node], 1.0f);
                v.x *= inv; v.y *= inv; v.z *= inv; v.w *= inv;
            } else if (node < N_NODES) {
                v = *reinterpret_cast<const float4*>(
                        x + (size_t)node * IN_CH + kc + j4 * 4);
            } else {
                v = make_float4(0.f, 0.f, 0.f, 0.f);
            }
            aregs[t] = v;
        }
        #pragma unroll
        for (int t = 0; t < 4; ++t) {
            int idx = tid + t * 256;
            int n = idx >> 3, j4 = idx & 7;
            bregs[t] = *reinterpret_cast<const float4*>(
                           g_Bt + (size_t)(nblk0 + n) * K_TOT + kofs + kc + j4 * 4);
        }
    };

    auto sts_chunk = [&](int buf) {
        float* As = (float*)(smem + OFF_A + buf * ABYTES);
        float* Bs = (float*)(smem + OFF_B + buf * ABYTES);
        #pragma unroll
        for (int t = 0; t < 4; ++t) {
            float4 v = aregs[t];
            float2 lo = make_float2(__uint_as_float(f2tf(v.x)), __uint_as_float(f2tf(v.y)));
            float2 hi = make_float2(__uint_as_float(f2tf(v.z)), __uint_as_float(f2tf(v.w)));
            *reinterpret_cast<float2*>(As + arow[t]) = lo;
            *reinterpret_cast<float2*>(As + arow[t] + 2) = hi;
        }
        #pragma unroll
        for (int t = 0; t < 4; ++t) {
            int idx = tid + t * 256;
            int n = idx >> 3, j4 = idx & 7;
            float4 v = bregs[t];            // already tf32
            *reinterpret_cast<float2*>(Bs + n * PAD + j4 * 4) = make_float2(v.x, v.y);
            *reinterpret_cast<float2*>(Bs + n * PAD + j4 * 4 + 2) = make_float2(v.z, v.w);
        }
    };

    float acc[2][8][4];
    #pragma unroll
    for (int mi = 0; mi < 2; ++mi)
        #pragma unroll
        for (int ni = 0; ni < 8; ++ni)
            #pragma unroll
            for (int j = 0; j < 4; ++j) acc[mi][ni][j] = 0.f;

    load_chunk(0);
    sts_chunk(0);
    __syncthreads();

    #pragma unroll
    for (int c = 0; c < 4; ++c) {          // K = 128 -> 4 chunks of 32
        const int buf = c & 1;
        if (c < 3) load_chunk(c + 1);

        const uint32_t sAc = smem_u32(smem + OFF_A + buf * ABYTES);
        const uint32_t sBc = smem_u32(smem + OFF_B + buf * ABYTES);
        #pragma unroll
        for (int ks = 0; ks < 4; ++ks) {
            const uint32_t kb = ks * 32;
            uint32_t a[2][4];
            ldsm_x4(a[0][0], a[0][1], a[0][2], a[0][3], sAc + aoff[0] + kb);
            ldsm_x4(a[1][0], a[1][1], a[1][2], a[1][3], sAc + aoff[1] + kb);
            #pragma unroll
            for (int p = 0; p < 4; ++p) {
                uint32_t b0, b1, b2, b3;
                ldsm_x4(b0, b1, b2, b3, sBc + boff[p] + kb);
                mma_tf32(acc[0][2 * p],     a[0], b0, b1);
                mma_tf32(acc[1][2 * p],     a[1], b0, b1);
                mma_tf32(acc[0][2 * p + 1], a[0], b2, b3);
                mma_tf32(acc[1][2 * p + 1], a[1], b2, b3);
            }
        }

        if (c < 3) {
            sts_chunk(buf ^ 1);
            __syncthreads();
        }
    }

    #pragma unroll
    for (int mi = 0; mi < 2; ++mi) {
        int row = node0 + m_base + mi * 16 + lrow;
        #pragma unroll
        for (int ni = 0; ni < 8; ++ni) {
            int col = n_base + ni * 8 + lane4 * 2;
            #pragma unroll
            for (int h = 0; h < 2; ++h) {
                int r = row + h * 8;
                if (r < N_NODES) {
                    float2* po = reinterpret_cast<float2*>(
                        out + (size_t)r * HID_CH + nblk0 + col);
                    float a0 = acc[mi][ni][2 * h], a1 = acc[mi][ni][2 * h + 1];
                    if (ACCUM_OUT) {
                        float2 cur = *po;
                        *po = make_float2(cur.x + a0, cur.y + a1);
                    } else {
                        *po = make_float2(a0 + bias_s[col], a1 + bias_s[col + 1]);
                    }
                }
            }
        }
    }
}

// ---------------------------------------------------------------------------
// Kernel 2 (fused): scatter (bid%3==0) || gemm1: out = x@W_r + b_l (others).
// Grid 1173. Scatter: 4-edge unrolled per warp (4x MLP).
// ---------------------------------------------------------------------------
__global__ void __launch_bounds__(256, 2)
fused1_kernel(const float* __restrict__ x,
              const int* __restrict__ edge_index,
              const float* __restrict__ b_l,
              float* __restrict__ out) {
    extern __shared__ char smem[];
    const int bid = blockIdx.x;

    if (bid % 3 == 0) {
        // ---- scatter role: s in 0..390, edges [s*EPB, min((s+1)*EPB, E)) ----
        const int s = bid / 3;
        const int start = s * EPB;
        const int end = min(start + EPB, N_EDGES);
        const int wid = threadIdx.x >> 5;
        const int lane = threadIdx.x & 31;

        for (int e0 = start + wid * 4; e0 < end; e0 += 32) {
            const int ne = min(4, end - e0);
            int srcs[4], dsts[4];
            float4 v[4];
            #pragma unroll
            for (int j = 0; j < 4; ++j)
                if (j < ne) {
                    srcs[j] = edge_index[e0 + j];
                    dsts[j] = edge_index[N_EDGES + e0 + j];
                }
            #pragma unroll
            for (int j = 0; j < 4; ++j)
                if (j < ne)
                    v[j] = reinterpret_cast<const float4*>(
                               x + (size_t)srcs[j] * IN_CH)[lane];
            #pragma unroll
            for (int j = 0; j < 4; ++j)
                if (j < ne) {
                    float* a = g_agg + (size_t)dsts[j] * IN_CH + lane * 4;
                    asm volatile("red.global.add.v4.f32 [%0], {%1, %2, %3, %4};"
                                 :: "l"(a), "f"(v[j].x), "f"(v[j].y),
                                    "f"(v[j].z), "f"(v[j].w) : "memory");
                    if (lane == 0) atomicAdd(&g_cnt[dsts[j]], 1.0f);
                }
        }
        return;
    }

    // ---- gemm role: g in 0..781 (non-multiples of 3 enumerated) ----
    const int gidx = bid - bid / 3 - 1;
    const int node0 = (gidx % N_TILES) * TILE_M;
    const int nblk0 = (gidx / N_TILES) * TILE_N;
    gemm_tile<false, false>(smem, node0, nblk0, IN_CH /* W_r half */, x, b_l, out);
}

// ---------------------------------------------------------------------------
// Kernel 3: gemm2 — out += mean @ W_l. Grid (391, 2).
// ---------------------------------------------------------------------------
__global__ void __launch_bounds__(256, 2)
gemm2_kernel(float* __restrict__ out) {
    extern __shared__ char smem[];
    const int node0 = blockIdx.x * TILE_M;
    const int nblk0 = blockIdx.y * TILE_N;
    gemm_tile<true, true>(smem, node0, nblk0, 0 /* W_l half */, nullptr, nullptr, out);
}

// ---------------------------------------------------------------------------
// Launch. Inputs: x f32[50000*128], edge_index i32[2*640000],
// W_l f32[128*256], b_l f32[256], W_r f32[128*256]. Out f32[50000*256].
// ---------------------------------------------------------------------------
extern "C" void kernel_launch(void* const* d_in, const int* in_sizes, int n_in,
                              void* d_out, int out_size) {
    const float* x = (const float*)d_in[0];
    const int* edge_index = (const int*)d_in[1];
    const float* W_l = (const float*)d_in[2];
    const float* b_l = (const float*)d_in[3];
    const float* W_r = (const float*)d_in[4];
    float* out = (float*)d_out;

    cudaFuncSetAttribute(fused1_kernel,
                         cudaFuncAttributeMaxDynamicSharedMemorySize, SMEM_BYTES);
    cudaFuncSetAttribute(gemm2_kernel,
                         cudaFuncAttributeMaxDynamicSharedMemorySize, SMEM_BYTES);

    prep_kernel<<<592, 256>>>(W_l, W_r);
    fused1_kernel<<<1173, 256, SMEM_BYTES>>>(x, edge_index, b_l, out);
    dim3 grid2(N_TILES, 2);
    gemm2_kernel<<<grid2, 256, SMEM_BYTES>>>(out);
}

// round 11
// speedup vs baseline: 1.1165x; 1.1165x over previous
#include <cuda_runtime.h>
#include <cstdint>

#define N_NODES 50000
#define N_PAD   50048           // 391 * 128
#define N_EDGES 640000
#define IN_CH   128
#define HID_CH  256
#define K_TOT   256
#define TILE_M  128
#define TILE_N  128
#define N_TILES 391             // ceil(50000/128)
#define CHUNK_K 32
#define PAD     36              // floats per smem row (16B-aligned, ldmatrix conflict-free)

// Scratch (__device__ globals zero-initialized; pad rows never RED'd).
__device__ float g_agg[N_PAD * IN_CH];
__device__ float g_cnt[N_PAD];
__device__ float g_Bt[HID_CH * K_TOT];   // Bt[n][k] = Wcat[k][n], tf32-rounded

__device__ __forceinline__ uint32_t f2tf(float f) {
    uint32_t r;
    asm("cvt.rna.tf32.f32 %0, %1;" : "=r"(r) : "f"(f));
    return r;
}
__device__ __forceinline__ uint32_t smem_u32(const void* p) {
    return (uint32_t)__cvta_generic_to_shared(p);
}
__device__ __forceinline__ void ldsm_x4(uint32_t& r0, uint32_t& r1,
                                        uint32_t& r2, uint32_t& r3, uint32_t addr) {
    asm volatile("ldmatrix.sync.aligned.m8n8.x4.shared.b16 {%0,%1,%2,%3}, [%4];"
                 : "=r"(r0), "=r"(r1), "=r"(r2), "=r"(r3) : "r"(addr));
}
__device__ __forceinline__ void mma_tf32(float* c, const uint32_t* a,
                                         uint32_t b0, uint32_t b1) {
    asm("mma.sync.aligned.m16n8k8.row.col.f32.tf32.tf32.f32 "
        "{%0,%1,%2,%3}, {%4,%5,%6,%7}, {%8,%9}, {%0,%1,%2,%3};"
        : "+f"(c[0]), "+f"(c[1]), "+f"(c[2]), "+f"(c[3])
        : "r"(a[0]), "r"(a[1]), "r"(a[2]), "r"(a[3]), "r"(b0), "r"(b1));
}

// ---------------------------------------------------------------------------
// Kernel 1: prep — zero accumulators + transpose weights (grid-stride roles).
// ---------------------------------------------------------------------------
__global__ void prep_kernel(const float* __restrict__ W_l,
                            const float* __restrict__ W_r) {
    int idx = blockIdx.x * blockDim.x + threadIdx.x;
    int stride = gridDim.x * blockDim.x;
    const int total4 = (N_PAD * IN_CH) / 4;
    float4 z = make_float4(0.f, 0.f, 0.f, 0.f);
    for (int i = idx; i < total4; i += stride)
        reinterpret_cast<float4*>(g_agg)[i] = z;
    for (int i = idx; i < N_PAD; i += stride) g_cnt[i] = 0.0f;
    for (int i = idx; i < HID_CH * K_TOT; i += stride) {
        int n = i >> 8, k = i & 255;   // K_TOT = 256
        float v = (k < IN_CH) ? W_l[k * HID_CH + n] : W_r[(k - IN_CH) * HID_CH + n];
        g_Bt[n * K_TOT + k] = __uint_as_float(f2tf(v));
    }
}

// ---------------------------------------------------------------------------
// Kernel 2: per-edge scatter: red.global.add.v4.f32 (R9 version, no smem).
// ---------------------------------------------------------------------------
__global__ void scatter_kernel(const float* __restrict__ x,
                               const int* __restrict__ edge_index) {
    int warp = (blockIdx.x * blockDim.x + threadIdx.x) >> 5;
    int lane = threadIdx.x & 31;
    if (warp >= N_EDGES) return;

    int src = edge_index[warp];
    int dst = edge_index[N_EDGES + warp];

    float4 v = reinterpret_cast<const float4*>(x + (size_t)src * IN_CH)[lane];
    float* a = g_agg + (size_t)dst * IN_CH + lane * 4;
    asm volatile("red.global.add.v4.f32 [%0], {%1, %2, %3, %4};"
                 :: "l"(a), "f"(v.x), "f"(v.y), "f"(v.z), "f"(v.w) : "memory");
    if (lane == 0) atomicAdd(&g_cnt[dst], 1.0f);
}

// ---------------------------------------------------------------------------
// Shared GEMM smem layout.
// ---------------------------------------------------------------------------
#define OFF_BIAS 0
#define OFF_A    512
#define ABYTES   (TILE_M * PAD * 4)        // 18432
#define OFF_B    (OFF_A + 2 * ABYTES)      // 37376
#define SMEM_BYTES (OFF_B + 2 * ABYTES)    // 74240

// ---------------------------------------------------------------------------
// GEMM tile body: C[128x128] = Asrc(K=128) @ g_Bt[:, kofs..kofs+128) (+bias).
// AGG_PATH: A = g_agg*inv(cnt) (padded, unguarded); else A = x (guarded).
// ACCUM_OUT: epilogue does out += acc (no bias); else out = acc + bias.
// (Validated in R10 — identical rel_err to R9.)
// ---------------------------------------------------------------------------
template <bool AGG_PATH, bool ACCUM_OUT>
__device__ __forceinline__ void gemm_tile(char* smem, int node0, int nblk0, int kofs,
                                          const float* __restrict__ x,
                                          const float* __restrict__ b_l,
                                          float* __restrict__ out) {
    const int tid = threadIdx.x;
    const int wid = tid >> 5, lid = tid & 31;
    const int lrow = lid >> 2, lane4 = lid & 3;
    const int m_base = (wid & 3) * 32;
    const int n_base = (wid >> 2) * 64;

    float* bias_s = (float*)(smem + OFF_BIAS);
    if (!ACCUM_OUT && tid < TILE_N) bias_s[tid] = b_l[nblk0 + tid];

    const int g = lid >> 3;
    const int rin = lid & 7;
    uint32_t aoff[2];
    #pragma unroll
    for (int mi = 0; mi < 2; ++mi)
        aoff[mi] = ((m_base + mi * 16 + (g & 1) * 8 + rin) * PAD + (g >> 1) * 4) * 4;
    uint32_t boff[4];
    #pragma unroll
    for (int p = 0; p < 4; ++p)
        boff[p] = ((n_base + p * 16 + (g >> 1) * 8 + rin) * PAD + (g & 1) * 4) * 4;

    float4 aregs[4], bregs[4];
    int arow[4];

    auto load_chunk = [&](int c) {
        const int kc = c * CHUNK_K;
        #pragma unroll
        for (int t = 0; t < 4; ++t) {
            int idx = tid + t * 256;
            int row = idx >> 3, j4 = idx & 7;
            int node = node0 + row;
            arow[t] = row * PAD + j4 * 4;
            float4 v;
            if (AGG_PATH) {
                v = *reinterpret_cast<const float4*>(
                        g_agg + (size_t)node * IN_CH + kc + j4 * 4);
                float inv = 1.0f / fmaxf(g_cnt[node], 1.0f);
                v.x *= inv; v.y *= inv; v.z *= inv; v.w *= inv;
            } else if (node < N_NODES) {
                v = *reinterpret_cast<const float4*>(
                        x + (size_t)node * IN_CH + kc + j4 * 4);
            } else {
                v = make_float4(0.f, 0.f, 0.f, 0.f);
            }
            aregs[t] = v;
        }
        #pragma unroll
        for (int t = 0; t < 4; ++t) {
            int idx = tid + t * 256;
            int n = idx >> 3, j4 = idx & 7;
            bregs[t] = *reinterpret_cast<const float4*>(
                           g_Bt + (size_t)(nblk0 + n) * K_TOT + kofs + kc + j4 * 4);
        }
    };

    auto sts_chunk = [&](int buf) {
        float* As = (float*)(smem + OFF_A + buf * ABYTES);
        float* Bs = (float*)(smem + OFF_B + buf * ABYTES);
        #pragma unroll
        for (int t = 0; t < 4; ++t) {
            float4 v = aregs[t];
            float2 lo = make_float2(__uint_as_float(f2tf(v.x)), __uint_as_float(f2tf(v.y)));
            float2 hi = make_float2(__uint_as_float(f2tf(v.z)), __uint_as_float(f2tf(v.w)));
            *reinterpret_cast<float2*>(As + arow[t]) = lo;
            *reinterpret_cast<float2*>(As + arow[t] + 2) = hi;
        }
        #pragma unroll
        for (int t = 0; t < 4; ++t) {
            int idx = tid + t * 256;
            int n = idx >> 3, j4 = idx & 7;
            float4 v = bregs[t];            // already tf32
            *reinterpret_cast<float2*>(Bs + n * PAD + j4 * 4) = make_float2(v.x, v.y);
            *reinterpret_cast<float2*>(Bs + n * PAD + j4 * 4 + 2) = make_float2(v.z, v.w);
        }
    };

    float acc[2][8][4];
    #pragma unroll
    for (int mi = 0; mi < 2; ++mi)
        #pragma unroll
        for (int ni = 0; ni < 8; ++ni)
            #pragma unroll
            for (int j = 0; j < 4; ++j) acc[mi][ni][j] = 0.f;

    load_chunk(0);
    sts_chunk(0);
    __syncthreads();

    #pragma unroll
    for (int c = 0; c < 4; ++c) {          // K = 128 -> 4 chunks of 32
        const int buf = c & 1;
        if (c < 3) load_chunk(c + 1);

        const uint32_t sAc = smem_u32(smem + OFF_A + buf * ABYTES);
        const uint32_t sBc = smem_u32(smem + OFF_B + buf * ABYTES);
        #pragma unroll
        for (int ks = 0; ks < 4; ++ks) {
            const uint32_t kb = ks * 32;
            uint32_t a[2][4];
            ldsm_x4(a[0][0], a[0][1], a[0][2], a[0][3], sAc + aoff[0] + kb);
            ldsm_x4(a[1][0], a[1][1], a[1][2], a[1][3], sAc + aoff[1] + kb);
            #pragma unroll
            for (int p = 0; p < 4; ++p) {
                uint32_t b0, b1, b2, b3;
                ldsm_x4(b0, b1, b2, b3, sBc + boff[p] + kb);
                mma_tf32(acc[0][2 * p],     a[0], b0, b1);
                mma_tf32(acc[1][2 * p],     a[1], b0, b1);
                mma_tf32(acc[0][2 * p + 1], a[0], b2, b3);
                mma_tf32(acc[1][2 * p + 1], a[1], b2, b3);
            }
        }

        if (c < 3) {
            sts_chunk(buf ^ 1);
            __syncthreads();
        }
    }

    #pragma unroll
    for (int mi = 0; mi < 2; ++mi) {
        int row = node0 + m_base + mi * 16 + lrow;
        #pragma unroll
        for (int ni = 0; ni < 8; ++ni) {
            int col = n_base + ni * 8 + lane4 * 2;
            #pragma unroll
            for (int h = 0; h < 2; ++h) {
                int r = row + h * 8;
                if (r < N_NODES) {
                    float2* po = reinterpret_cast<float2*>(
                        out + (size_t)r * HID_CH + nblk0 + col);
                    float a0 = acc[mi][ni][2 * h], a1 = acc[mi][ni][2 * h + 1];
                    if (ACCUM_OUT) {
                        float2 cur = *po;
                        *po = make_float2(cur.x + a0, cur.y + a1);
                    } else {
                        *po = make_float2(a0 + bias_s[col], a1 + bias_s[col + 1]);
                    }
                }
            }
        }
    }
}

// ---------------------------------------------------------------------------
// Kernel 3: gemm1 — out = x @ W_r + b_l (independent of scatter). Grid (391,2).
// ---------------------------------------------------------------------------
__global__ void __launch_bounds__(256, 2)
gemm1_kernel(const float* __restrict__ x,
             const float* __restrict__ b_l,
             float* __restrict__ out) {
    extern __shared__ char smem[];
    gemm_tile<false, false>(smem, blockIdx.x * TILE_M, blockIdx.y * TILE_N,
                            IN_CH /* W_r half of Bt */, x, b_l, out);
}

// ---------------------------------------------------------------------------
// Kernel 4: gemm2 — out += mean @ W_l. Grid (391, 2).
// ---------------------------------------------------------------------------
__global__ void __launch_bounds__(256, 2)
gemm2_kernel(float* __restrict__ out) {
    extern __shared__ char smem[];
    gemm_tile<true, true>(smem, blockIdx.x * TILE_M, blockIdx.y * TILE_N,
                          0 /* W_l half of Bt */, nullptr, nullptr, out);
}

// ---------------------------------------------------------------------------
// Launch: stream fork-join so scatter (L2-bound) overlaps gemm1 (tensor-bound).
// Graph-capture-legal: fork/join via events, all work rejoins stream 0.
// Inputs: x f32[50000*128], edge_index i32[2*640000],
// W_l f32[128*256], b_l f32[256], W_r f32[128*256]. Out f32[50000*256].
// ---------------------------------------------------------------------------
extern "C" void kernel_launch(void* const* d_in, const int* in_sizes, int n_in,
                              void* d_out, int out_size) {
    const float* x = (const float*)d_in[0];
    const int* edge_index = (const int*)d_in[1];
    const float* W_l = (const float*)d_in[2];
    const float* b_l = (const float*)d_in[3];
    const float* W_r = (const float*)d_in[4];
    float* out = (float*)d_out;

    cudaFuncSetAttribute(gemm1_kernel,
                         cudaFuncAttributeMaxDynamicSharedMemorySize, SMEM_BYTES);
    cudaFuncSetAttribute(gemm2_kernel,
                         cudaFuncAttributeMaxDynamicSharedMemorySize, SMEM_BYTES);

    cudaStream_t s2;
    cudaStreamCreateWithFlags(&s2, cudaStreamNonBlocking);
    cudaEvent_t ev_fork, ev_join;
    cudaEventCreateWithFlags(&ev_fork, cudaEventDisableTiming);
    cudaEventCreateWithFlags(&ev_join, cudaEventDisableTiming);

    // Stage 0: prep (stream 0).
    prep_kernel<<<592, 256>>>(W_l, W_r);

    // Fork: s2 joins the capture via event dependency on stream 0.
    cudaEventRecord(ev_fork, 0);
    cudaStreamWaitEvent(s2, ev_fork, 0);

    // Concurrent: scatter on stream 0, gemm1 on s2.
    scatter_kernel<<<(N_EDGES + 7) / 8, 256>>>(x, edge_index);
    dim3 grid(N_TILES, 2);
    gemm1_kernel<<<grid, 256, SMEM_BYTES, s2>>>(x, b_l, out);

    // Join: stream 0 waits for gemm1 before gemm2 (scatter order is implicit).
    cudaEventRecord(ev_join, s2);
    cudaStreamWaitEvent(0, ev_join, 0);

    gemm2_kernel<<<grid, 256, SMEM_BYTES>>>(out);
}

// round 12
// speedup vs baseline: 1.3564x; 1.2149x over previous
#include <cuda_runtime.h>
#include <cstdint>

#define N_NODES 50000
#define N_PAD   50048           // 391 * 128
#define N_EDGES 640000
#define IN_CH   128
#define HID_CH  256
#define K_TOT   256
#define TILE_M  128
#define TILE_N  128
#define N_TILES 391             // ceil(50000/128)
#define CHUNK_K 32
#define N_CHUNKS 8
#define STAGES  3
#define PAD     36              // floats per smem row (16B-aligned, ldmatrix conflict-free)

// Scratch (__device__ globals zero-initialized; pad rows never RED'd -> stay 0).
__device__ float g_agg[N_PAD * IN_CH];
__device__ float g_cnt[N_PAD];
__device__ float g_Bt[HID_CH * K_TOT];   // Bt[n][k] = Wcat[k][n], tf32-rounded (RNA)

__device__ __forceinline__ uint32_t f2tf(float f) {
    uint32_t r;
    asm("cvt.rna.tf32.f32 %0, %1;" : "=r"(r) : "f"(f));
    return r;
}
__device__ __forceinline__ uint32_t smem_u32(const void* p) {
    return (uint32_t)__cvta_generic_to_shared(p);
}
__device__ __forceinline__ void cp16(uint32_t dst, const void* src) {
    asm volatile("cp.async.ca.shared.global [%0], [%1], 16;"
                 :: "r"(dst), "l"(src) : "memory");
}
// Zero-fill variant: src_size=0 writes zeros (used for x rows past N_NODES).
__device__ __forceinline__ void cp16_zfill(uint32_t dst, const void* src, int ok) {
    asm volatile("cp.async.ca.shared.global [%0], [%1], 16, %2;"
                 :: "r"(dst), "l"(src), "r"(ok ? 16 : 0) : "memory");
}
__device__ __forceinline__ void ldsm_x4(uint32_t& r0, uint32_t& r1,
                                        uint32_t& r2, uint32_t& r3, uint32_t addr) {
    asm volatile("ldmatrix.sync.aligned.m8n8.x4.shared.b16 {%0,%1,%2,%3}, [%4];"
                 : "=r"(r0), "=r"(r1), "=r"(r2), "=r"(r3) : "r"(addr));
}
__device__ __forceinline__ void mma_tf32(float* c, const uint32_t* a,
                                         uint32_t b0, uint32_t b1) {
    asm("mma.sync.aligned.m16n8k8.row.col.f32.tf32.tf32.f32 "
        "{%0,%1,%2,%3}, {%4,%5,%6,%7}, {%8,%9}, {%0,%1,%2,%3};"
        : "+f"(c[0]), "+f"(c[1]), "+f"(c[2]), "+f"(c[3])
        : "r"(a[0]), "r"(a[1]), "r"(a[2]), "r"(a[3]), "r"(b0), "r"(b1));
}

// ---------------------------------------------------------------------------
// Kernel 1: prep — zero accumulators + transpose weights (grid-stride roles).
// ---------------------------------------------------------------------------
__global__ void prep_kernel(const float* __restrict__ W_l,
                            const float* __restrict__ W_r) {
    int idx = blockIdx.x * blockDim.x + threadIdx.x;
    int stride = gridDim.x * blockDim.x;
    const int total4 = (N_PAD * IN_CH) / 4;
    float4 z = make_float4(0.f, 0.f, 0.f, 0.f);
    for (int i = idx; i < total4; i += stride)
        reinterpret_cast<float4*>(g_agg)[i] = z;
    for (int i = idx; i < N_PAD; i += stride) g_cnt[i] = 0.0f;
    for (int i = idx; i < HID_CH * K_TOT; i += stride) {
        int n = i >> 8, k = i & 255;   // K_TOT = 256
        float v = (k < IN_CH) ? W_l[k * HID_CH + n] : W_r[(k - IN_CH) * HID_CH + n];
        g_Bt[n * K_TOT + k] = __uint_as_float(f2tf(v));
    }
}

// ---------------------------------------------------------------------------
// Kernel 2: per-edge scatter: red.global.add.v4.f32 (at L2 RED ceiling, 71us).
// ---------------------------------------------------------------------------
__global__ void scatter_kernel(const float* __restrict__ x,
                               const int* __restrict__ edge_index) {
    int warp = (blockIdx.x * blockDim.x + threadIdx.x) >> 5;
    int lane = threadIdx.x & 31;
    if (warp >= N_EDGES) return;

    int src = edge_index[warp];
    int dst = edge_index[N_EDGES + warp];

    float4 v = reinterpret_cast<const float4*>(x + (size_t)src * IN_CH)[lane];
    float* a = g_agg + (size_t)dst * IN_CH + lane * 4;
    asm volatile("red.global.add.v4.f32 [%0], {%1, %2, %3, %4};"
                 :: "l"(a), "f"(v.x), "f"(v.y), "f"(v.z), "f"(v.w) : "memory");
    if (lane == 0) atomicAdd(&g_cnt[dst], 1.0f);
}

// ---------------------------------------------------------------------------
// Kernel 3: fused tf32 GEMM — cp.async 3-stage + ldmatrix + fragment scaling.
// Block 128x128 tile, grid (391, 2). 8 warps = 4(M) x 2(N); warp tile 32x64.
// Chunks c<4: A = g_agg (raw sums; inv(cnt) applied to A-fragments post-ldsm,
// legal because row-scaling commutes with the GEMM). Chunks c>=4: A = x.
// mma's hardware tf32 truncation replaces explicit RNA rounding on A.
// ---------------------------------------------------------------------------
#define OFF_BIAS 0
#define OFF_STAGE 512
#define A_BYTES  (TILE_M * PAD * 4)                 // 18432
#define STAGE_BYTES (2 * A_BYTES)                   // A + B per stage: 36864
#define SMEM_BYTES (OFF_STAGE + STAGES * STAGE_BYTES)  // 111104 (x2 CTA = 222KB)

__global__ void __launch_bounds__(256, 2)
gemm_kernel(const float* __restrict__ x,
            const float* __restrict__ b_l,
            float* __restrict__ out) {
    extern __shared__ char smem[];
    const int tid = threadIdx.x;
    const int wid = tid >> 5, lid = tid & 31;
    const int lrow = lid >> 2, lane4 = lid & 3;
    const int node0 = blockIdx.x * TILE_M;
    const int nblk0 = blockIdx.y * TILE_N;
    const int m_base = (wid & 3) * 32;
    const int n_base = (wid >> 2) * 64;

    float* bias_s = (float*)(smem + OFF_BIAS);
    if (tid < TILE_N) bias_s[tid] = b_l[nblk0 + tid];

    // Per-thread inv(cnt) for the 4 M-rows this thread's A-fragments cover.
    // Rows: m_base + mi*16 + lrow + {0,8}.  g_cnt padded -> unguarded.
    float inv[2][2];
    #pragma unroll
    for (int mi = 0; mi < 2; ++mi)
        #pragma unroll
        for (int h = 0; h < 2; ++h)
            inv[mi][h] = 1.0f / fmaxf(g_cnt[node0 + m_base + mi * 16 + lrow + h * 8], 1.0f);

    // ldmatrix lane-address components (validated in R9).
    const int g = lid >> 3;
    const int rin = lid & 7;
    uint32_t aoff[2];
    #pragma unroll
    for (int mi = 0; mi < 2; ++mi)
        aoff[mi] = ((m_base + mi * 16 + (g & 1) * 8 + rin) * PAD + (g >> 1) * 4) * 4;
    uint32_t boff[4];
    #pragma unroll
    for (int p = 0; p < 4; ++p)
        boff[p] = ((n_base + p * 16 + (g >> 1) * 8 + rin) * PAD + (g & 1) * 4) * 4;

    // cp.async mapping: 1024 granules (16B) per operand per chunk; 4 per thread.
    // Thread t, rep r: granule idx = t + r*256 -> row = idx>>3, j4 = idx&7.
    const uint32_t sbase = smem_u32(smem + OFF_STAGE);
    int rows[4], j4s[4];
    uint32_t sdst[4];
    #pragma unroll
    for (int t = 0; t < 4; ++t) {
        int idx = tid + t * 256;
        rows[t] = idx >> 3;
        j4s[t] = idx & 7;
        sdst[t] = (uint32_t)(rows[t] * PAD + j4s[t] * 4) * 4;
    }

    auto issue = [&](int c) {
        const uint32_t so = (uint32_t)(c % STAGES) * STAGE_BYTES;
        if (c < 4) {
            const int kc = c * CHUNK_K;
            #pragma unroll
            for (int t = 0; t < 4; ++t)   // A from g_agg (padded, unguarded)
                cp16(sbase + so + sdst[t],
                     g_agg + (size_t)(node0 + rows[t]) * IN_CH + kc + j4s[t] * 4);
        } else {
            const int kc = (c - 4) * CHUNK_K;
            #pragma unroll
            for (int t = 0; t < 4; ++t) { // A from x (zfill past N_NODES)
                int node = node0 + rows[t];
                int ok = node < N_NODES;
                cp16_zfill(sbase + so + sdst[t],
                           x + (size_t)(ok ? node : 0) * IN_CH + kc + j4s[t] * 4, ok);
            }
        }
        const int kb = c * CHUNK_K;
        #pragma unroll
        for (int t = 0; t < 4; ++t)       // B from g_Bt
            cp16(sbase + so + A_BYTES + sdst[t],
                 g_Bt + (size_t)(nblk0 + rows[t]) * K_TOT + kb + j4s[t] * 4);
    };

    float acc[2][8][4];
    #pragma unroll
    for (int mi = 0; mi < 2; ++mi)
        #pragma unroll
        for (int ni = 0; ni < 8; ++ni)
            #pragma unroll
            for (int j = 0; j < 4; ++j) acc[mi][ni][j] = 0.f;

    issue(0); asm volatile("cp.async.commit_group;" ::: "memory");
    issue(1); asm volatile("cp.async.commit_group;" ::: "memory");

    #pragma unroll
    for (int c = 0; c < N_CHUNKS; ++c) {
        asm volatile("cp.async.wait_group 1;" ::: "memory");
        __syncthreads();

        if (c + 2 < N_CHUNKS) issue(c + 2);
        asm volatile("cp.async.commit_group;" ::: "memory");

        const uint32_t sAc = sbase + (uint32_t)(c % STAGES) * STAGE_BYTES;
        const uint32_t sBc = sAc + A_BYTES;
        #pragma unroll
        for (int ks = 0; ks < 4; ++ks) {
            const uint32_t kb = ks * 32;
            uint32_t a[2][4];
            ldsm_x4(a[0][0], a[0][1], a[0][2], a[0][3], sAc + aoff[0] + kb);
            ldsm_x4(a[1][0], a[1][1], a[1][2], a[1][3], sAc + aoff[1] + kb);
            if (c < 4) {   // agg chunks: scale fragments by per-row inv(cnt)
                #pragma unroll
                for (int mi = 0; mi < 2; ++mi) {
                    a[mi][0] = __float_as_uint(__uint_as_float(a[mi][0]) * inv[mi][0]);
                    a[mi][1] = __float_as_uint(__uint_as_float(a[mi][1]) * inv[mi][1]);
                    a[mi][2] = __float_as_uint(__uint_as_float(a[mi][2]) * inv[mi][0]);
                    a[mi][3] = __float_as_uint(__uint_as_float(a[mi][3]) * inv[mi][1]);
                }
            }
            #pragma unroll
            for (int p = 0; p < 4; ++p) {
                uint32_t b0, b1, b2, b3;
                ldsm_x4(b0, b1, b2, b3, sBc + boff[p] + kb);
                mma_tf32(acc[0][2 * p],     a[0], b0, b1);
                mma_tf32(acc[1][2 * p],     a[1], b0, b1);
                mma_tf32(acc[0][2 * p + 1], a[0], b2, b3);
                mma_tf32(acc[1][2 * p + 1], a[1], b2, b3);
            }
        }
        __syncthreads();
    }

    // ---- epilogue: bias + store ----
    #pragma unroll
    for (int mi = 0; mi < 2; ++mi) {
        int row = node0 + m_base + mi * 16 + lrow;
        #pragma unroll
        for (int ni = 0; ni < 8; ++ni) {
            int col = n_base + ni * 8 + lane4 * 2;
            float b0 = bias_s[col], b1 = bias_s[col + 1];
            if (row < N_NODES) {
                *reinterpret_cast<float2*>(out + (size_t)row * HID_CH + nblk0 + col) =
                    make_float2(acc[mi][ni][0] + b0, acc[mi][ni][1] + b1);
            }
            if (row + 8 < N_NODES) {
                *reinterpret_cast<float2*>(out + (size_t)(row + 8) * HID_CH + nblk0 + col) =
                    make_float2(acc[mi][ni][2] + b0, acc[mi][ni][3] + b1);
            }
        }
    }
}

// ---------------------------------------------------------------------------
// Launch. Inputs: x f32[50000*128], edge_index i32[2*640000],
// W_l f32[128*256], b_l f32[256], W_r f32[128*256]. Out f32[50000*256].
// ---------------------------------------------------------------------------
extern "C" void kernel_launch(void* const* d_in, const int* in_sizes, int n_in,
                              void* d_out, int out_size) {
    const float* x = (const float*)d_in[0];
    const int* edge_index = (const int*)d_in[1];
    const float* W_l = (const float*)d_in[2];
    const float* b_l = (const float*)d_in[3];
    const float* W_r = (const float*)d_in[4];
    float* out = (float*)d_out;

    cudaFuncSetAttribute(gemm_kernel,
                         cudaFuncAttributeMaxDynamicSharedMemorySize, SMEM_BYTES);

    prep_kernel<<<592, 256>>>(W_l, W_r);
    scatter_kernel<<<(N_EDGES + 7) / 8, 256>>>(x, edge_index);

    dim3 grid(N_TILES, 2);
    gemm_kernel<<<grid, 256, SMEM_BYTES>>>(x, b_l, out);
}

// round 13
// speedup vs baseline: 1.4989x; 1.1051x over previous
#include <cuda_runtime.h>
#include <cstdint>

#define N_NODES 50000
#define N_PAD   50048           // 391 * 128
#define N_EDGES 640000
#define IN_CH   128
#define HID_CH  256
#define K_TOT   256
#define TILE_M  128
#define TILE_N  128
#define N_TILES 391             // ceil(50000/128)
#define CHUNK_K 32
#define N_CHUNKS 8
#define STAGES  3
#define PAD     36              // floats per smem row (16B-aligned, ldmatrix conflict-free)

// Scratch (__device__ globals zero-initialized; pad rows never RED'd -> stay 0).
__device__ float g_agg[N_PAD * IN_CH];
__device__ float g_cnt[N_PAD];
__device__ float g_Bt[HID_CH * K_TOT];   // Bt[n][k] = Wcat[k][n], tf32-rounded (RNA)

__device__ __forceinline__ uint32_t f2tf(float f) {
    uint32_t r;
    asm("cvt.rna.tf32.f32 %0, %1;" : "=r"(r) : "f"(f));
    return r;
}
__device__ __forceinline__ uint32_t smem_u32(const void* p) {
    return (uint32_t)__cvta_generic_to_shared(p);
}
__device__ __forceinline__ void cp16(uint32_t dst, const void* src) {
    asm volatile("cp.async.ca.shared.global [%0], [%1], 16;"
                 :: "r"(dst), "l"(src) : "memory");
}
// Zero-fill variant: src_size=0 writes zeros (used for x rows past N_NODES).
__device__ __forceinline__ void cp16_zfill(uint32_t dst, const void* src, int ok) {
    asm volatile("cp.async.ca.shared.global [%0], [%1], 16, %2;"
                 :: "r"(dst), "l"(src), "r"(ok ? 16 : 0) : "memory");
}
__device__ __forceinline__ void ldsm_x4(uint32_t& r0, uint32_t& r1,
                                        uint32_t& r2, uint32_t& r3, uint32_t addr) {
    asm volatile("ldmatrix.sync.aligned.m8n8.x4.shared.b16 {%0,%1,%2,%3}, [%4];"
                 : "=r"(r0), "=r"(r1), "=r"(r2), "=r"(r3) : "r"(addr));
}
__device__ __forceinline__ void mma_tf32(float* c, const uint32_t* a,
                                         uint32_t b0, uint32_t b1) {
    asm("mma.sync.aligned.m16n8k8.row.col.f32.tf32.tf32.f32 "
        "{%0,%1,%2,%3}, {%4,%5,%6,%7}, {%8,%9}, {%0,%1,%2,%3};"
        : "+f"(c[0]), "+f"(c[1]), "+f"(c[2]), "+f"(c[3])
        : "r"(a[0]), "r"(a[1]), "r"(a[2]), "r"(a[3]), "r"(b0), "r"(b1));
}

// ---------------------------------------------------------------------------
// Kernel 1: prep — zero accumulators + transpose weights (grid-stride roles).
// ---------------------------------------------------------------------------
__global__ void prep_kernel(const float* __restrict__ W_l,
                            const float* __restrict__ W_r) {
    int idx = blockIdx.x * blockDim.x + threadIdx.x;
    int stride = gridDim.x * blockDim.x;
    const int total4 = (N_PAD * IN_CH) / 4;
    float4 z = make_float4(0.f, 0.f, 0.f, 0.f);
    for (int i = idx; i < total4; i += stride)
        reinterpret_cast<float4*>(g_agg)[i] = z;
    for (int i = idx; i < N_PAD; i += stride) g_cnt[i] = 0.0f;
    for (int i = idx; i < HID_CH * K_TOT; i += stride) {
        int n = i >> 8, k = i & 255;   // K_TOT = 256
        float v = (k < IN_CH) ? W_l[k * HID_CH + n] : W_r[(k - IN_CH) * HID_CH + n];
        g_Bt[n * K_TOT + k] = __uint_as_float(f2tf(v));
    }
}

// ---------------------------------------------------------------------------
// Kernel 2: scatter — 4-edge unrolled per warp, 8 iterations per warp.
// Grid 2500 x 256: 2500 blocks * 8 warps * 4 edges * 8 iters = 640000 exact.
// 4x MLP per warp + 32x fewer blocks than the 1-edge/warp version.
// ---------------------------------------------------------------------------
__global__ void __launch_bounds__(256)
scatter_kernel(const float* __restrict__ x,
               const int* __restrict__ edge_index) {
    const int wid = threadIdx.x >> 5;
    const int lane = threadIdx.x & 31;
    const int base = blockIdx.x * 256;

    #pragma unroll
    for (int it = 0; it < 8; ++it) {
        const int e0 = base + it * 32 + wid * 4;
        int srcs[4], dsts[4];
        float4 v[4];
        #pragma unroll
        for (int j = 0; j < 4; ++j) {
            srcs[j] = edge_index[e0 + j];
            dsts[j] = edge_index[N_EDGES + e0 + j];
        }
        #pragma unroll
        for (int j = 0; j < 4; ++j)
            v[j] = reinterpret_cast<const float4*>(x + (size_t)srcs[j] * IN_CH)[lane];
        #pragma unroll
        for (int j = 0; j < 4; ++j) {
            float* a = g_agg + (size_t)dsts[j] * IN_CH + lane * 4;
            asm volatile("red.global.add.v4.f32 [%0], {%1, %2, %3, %4};"
                         :: "l"(a), "f"(v[j].x), "f"(v[j].y),
                            "f"(v[j].z), "f"(v[j].w) : "memory");
            if (lane == 0) atomicAdd(&g_cnt[dsts[j]], 1.0f);
        }
    }
}

// ---------------------------------------------------------------------------
// Kernel 3: fused tf32 GEMM — cp.async 3-stage + ldmatrix + fragment scaling.
// Block 128x128 tile, grid (391, 2). 8 warps = 4(M) x 2(N); warp tile 32x64.
// ONE __syncthreads per chunk (trailing barrier proven redundant: iter c+1's
// barrier orders stage-c reads before issue(c+3) rewrites that buffer).
// ---------------------------------------------------------------------------
#define OFF_BIAS 0
#define OFF_STAGE 512
#define A_BYTES  (TILE_M * PAD * 4)                 // 18432
#define STAGE_BYTES (2 * A_BYTES)                   // A + B per stage: 36864
#define SMEM_BYTES (OFF_STAGE + STAGES * STAGE_BYTES)  // 111104 (x2 CTA = 222KB)

__global__ void __launch_bounds__(256, 2)
gemm_kernel(const float* __restrict__ x,
            const float* __restrict__ b_l,
            float* __restrict__ out) {
    extern __shared__ char smem[];
    const int tid = threadIdx.x;
    const int wid = tid >> 5, lid = tid & 31;
    const int lrow = lid >> 2, lane4 = lid & 3;
    const int node0 = blockIdx.x * TILE_M;
    const int nblk0 = blockIdx.y * TILE_N;
    const int m_base = (wid & 3) * 32;
    const int n_base = (wid >> 2) * 64;

    float* bias_s = (float*)(smem + OFF_BIAS);
    if (tid < TILE_N) bias_s[tid] = b_l[nblk0 + tid];

    // Per-thread inv(cnt) for the 4 M-rows this thread's A-fragments cover.
    float inv[2][2];
    #pragma unroll
    for (int mi = 0; mi < 2; ++mi)
        #pragma unroll
        for (int h = 0; h < 2; ++h)
            inv[mi][h] = 1.0f / fmaxf(g_cnt[node0 + m_base + mi * 16 + lrow + h * 8], 1.0f);

    // ldmatrix lane-address components (validated R9/R12).
    const int g = lid >> 3;
    const int rin = lid & 7;
    uint32_t aoff[2];
    #pragma unroll
    for (int mi = 0; mi < 2; ++mi)
        aoff[mi] = ((m_base + mi * 16 + (g & 1) * 8 + rin) * PAD + (g >> 1) * 4) * 4;
    uint32_t boff[4];
    #pragma unroll
    for (int p = 0; p < 4; ++p)
        boff[p] = ((n_base + p * 16 + (g >> 1) * 8 + rin) * PAD + (g & 1) * 4) * 4;

    // cp.async mapping: 1024 granules (16B) per operand per chunk; 4 per thread.
    const uint32_t sbase = smem_u32(smem + OFF_STAGE);
    int rows[4], j4s[4];
    uint32_t sdst[4];
    #pragma unroll
    for (int t = 0; t < 4; ++t) {
        int idx = tid + t * 256;
        rows[t] = idx >> 3;
        j4s[t] = idx & 7;
        sdst[t] = (uint32_t)(rows[t] * PAD + j4s[t] * 4) * 4;
    }

    auto issue = [&](int c) {
        const uint32_t so = (uint32_t)(c % STAGES) * STAGE_BYTES;
        if (c < 4) {
            const int kc = c * CHUNK_K;
            #pragma unroll
            for (int t = 0; t < 4; ++t)   // A from g_agg (padded, unguarded)
                cp16(sbase + so + sdst[t],
                     g_agg + (size_t)(node0 + rows[t]) * IN_CH + kc + j4s[t] * 4);
        } else {
            const int kc = (c - 4) * CHUNK_K;
            #pragma unroll
            for (int t = 0; t < 4; ++t) { // A from x (zfill past N_NODES)
                int node = node0 + rows[t];
                int ok = node < N_NODES;
                cp16_zfill(sbase + so + sdst[t],
                           x + (size_t)(ok ? node : 0) * IN_CH + kc + j4s[t] * 4, ok);
            }
        }
        const int kb = c * CHUNK_K;
        #pragma unroll
        for (int t = 0; t < 4; ++t)       // B from g_Bt
            cp16(sbase + so + A_BYTES + sdst[t],
                 g_Bt + (size_t)(nblk0 + rows[t]) * K_TOT + kb + j4s[t] * 4);
    };

    float acc[2][8][4];
    #pragma unroll
    for (int mi = 0; mi < 2; ++mi)
        #pragma unroll
        for (int ni = 0; ni < 8; ++ni)
            #pragma unroll
            for (int j = 0; j < 4; ++j) acc[mi][ni][j] = 0.f;

    issue(0); asm volatile("cp.async.commit_group;" ::: "memory");
    issue(1); asm volatile("cp.async.commit_group;" ::: "memory");

    #pragma unroll
    for (int c = 0; c < N_CHUNKS; ++c) {
        asm volatile("cp.async.wait_group 1;" ::: "memory");
        __syncthreads();   // single barrier per chunk (see header comment)

        if (c + 2 < N_CHUNKS) issue(c + 2);
        asm volatile("cp.async.commit_group;" ::: "memory");

        const uint32_t sAc = sbase + (uint32_t)(c % STAGES) * STAGE_BYTES;
        const uint32_t sBc = sAc + A_BYTES;
        #pragma unroll
        for (int ks = 0; ks < 4; ++ks) {
            const uint32_t kb = ks * 32;
            uint32_t a[2][4];
            ldsm_x4(a[0][0], a[0][1], a[0][2], a[0][3], sAc + aoff[0] + kb);
            ldsm_x4(a[1][0], a[1][1], a[1][2], a[1][3], sAc + aoff[1] + kb);
            if (c < 4) {   // agg chunks: scale fragments by per-row inv(cnt)
                #pragma unroll
                for (int mi = 0; mi < 2; ++mi) {
                    a[mi][0] = __float_as_uint(__uint_as_float(a[mi][0]) * inv[mi][0]);
                    a[mi][1] = __float_as_uint(__uint_as_float(a[mi][1]) * inv[mi][1]);
                    a[mi][2] = __float_as_uint(__uint_as_float(a[mi][2]) * inv[mi][0]);
                    a[mi][3] = __float_as_uint(__uint_as_float(a[mi][3]) * inv[mi][1]);
                }
            }
            #pragma unroll
            for (int p = 0; p < 4; ++p) {
                uint32_t b0, b1, b2, b3;
                ldsm_x4(b0, b1, b2, b3, sBc + boff[p] + kb);
                mma_tf32(acc[0][2 * p],     a[0], b0, b1);
                mma_tf32(acc[1][2 * p],     a[1], b0, b1);
                mma_tf32(acc[0][2 * p + 1], a[0], b2, b3);
                mma_tf32(acc[1][2 * p + 1], a[1], b2, b3);
            }
        }
    }

    // ---- epilogue: bias + store ----
    #pragma unroll
    for (int mi = 0; mi < 2; ++mi) {
        int row = node0 + m_base + mi * 16 + lrow;
        #pragma unroll
        for (int ni = 0; ni < 8; ++ni) {
            int col = n_base + ni * 8 + lane4 * 2;
            float b0 = bias_s[col], b1 = bias_s[col + 1];
            if (row < N_NODES) {
                *reinterpret_cast<float2*>(out + (size_t)row * HID_CH + nblk0 + col) =
                    make_float2(acc[mi][ni][0] + b0, acc[mi][ni][1] + b1);
            }
            if (row + 8 < N_NODES) {
                *reinterpret_cast<float2*>(out + (size_t)(row + 8) * HID_CH + nblk0 + col) =
                    make_float2(acc[mi][ni][2] + b0, acc[mi][ni][3] + b1);
            }
        }
    }
}

// ---------------------------------------------------------------------------
// Launch. Inputs: x f32[50000*128], edge_index i32[2*640000],
// W_l f32[128*256], b_l f32[256], W_r f32[128*256]. Out f32[50000*256].
// ---------------------------------------------------------------------------
extern "C" void kernel_launch(void* const* d_in, const int* in_sizes, int n_in,
                              void* d_out, int out_size) {
    const float* x = (const float*)d_in[0];
    const int* edge_index = (const int*)d_in[1];
    const float* W_l = (const float*)d_in[2];
    const float* b_l = (const float*)d_in[3];
    const float* W_r = (const float*)d_in[4];
    float* out = (float*)d_out;

    cudaFuncSetAttribute(gemm_kernel,
                         cudaFuncAttributeMaxDynamicSharedMemorySize, SMEM_BYTES);

    prep_kernel<<<592, 256>>>(W_l, W_r);
    scatter_kernel<<<2500, 256>>>(x, edge_index);

    dim3 grid(N_TILES, 2);
    gemm_kernel<<<grid, 256, SMEM_BYTES>>>(x, b_l, out);
}